// round 3
// baseline (speedup 1.0000x reference)
#include <cuda_runtime.h>

// FastText embedding-bag:
//   out[b, :] = W_in[center_ids[b], :] + sum_{i: seg[i]==b} W_sub[ngram_idx[i], :]
// seg sorted ascending -> per-bag contiguous range via binary search.
// D = 300 floats = 75 float4 per row.
//
// R3: unroll-8 row gather with 8 live value registers (deep MLP window),
//     int offsets, wv load overlapped with the binary search,
//     uniform-predicated tail (no extra traffic, no divergence).

#define D4 75
#define CHUNK 96

__global__ void __launch_bounds__(96)
ft_bag_kernel(const int* __restrict__ center,
              const int* __restrict__ ngram,
              const int* __restrict__ seg,
              const float4* __restrict__ Win,
              const float4* __restrict__ Wsub,
              float4* __restrict__ out,
              int total)
{
    const int b = blockIdx.x;
    const int t = threadIdx.x;
    const bool act = (t < D4);

    __shared__ int s_lo, s_hi;
    __shared__ int s_idx[CHUNK];

    // word vector load issued FIRST — overlaps the binary search latency
    float4 acc = make_float4(0.f, 0.f, 0.f, 0.f);
    if (act) {
        const int crow = __ldg(center + b) * D4;   // < 7.5M, fits int
        acc = __ldg(Win + crow + t);
    }

    // two threads run the two lower_bound searches in parallel
    if (t < 2) {
        const int target = b + t;
        int lo = 0, hi = total;
        while (lo < hi) {
            int m = (lo + hi) >> 1;
            if (__ldg(seg + m) < target) lo = m + 1;
            else                         hi = m;
        }
        if (t == 0) s_lo = lo; else s_hi = lo;
    }
    __syncthreads();

    const int lo = s_lo;
    const int hi = s_hi;

    for (int base = lo; base < hi; base += CHUNK) {
        const int n = min(hi - base, CHUNK);

        if (base != lo) __syncthreads();          // protect s_idx reuse
        if (t < n) s_idx[t] = __ldg(ngram + base + t);
        __syncthreads();

        if (act) {
            int j = 0;

            // hot path: full groups of 8 independent LDG.128
            #pragma unroll 1
            for (; j + 8 <= n; j += 8) {
                const int r0 = s_idx[j + 0] * D4;
                const int r1 = s_idx[j + 1] * D4;
                const int r2 = s_idx[j + 2] * D4;
                const int r3 = s_idx[j + 3] * D4;
                const int r4 = s_idx[j + 4] * D4;
                const int r5 = s_idx[j + 5] * D4;
                const int r6 = s_idx[j + 6] * D4;
                const int r7 = s_idx[j + 7] * D4;
                float4 v0 = __ldg(Wsub + r0 + t);
                float4 v1 = __ldg(Wsub + r1 + t);
                float4 v2 = __ldg(Wsub + r2 + t);
                float4 v3 = __ldg(Wsub + r3 + t);
                float4 v4 = __ldg(Wsub + r4 + t);
                float4 v5 = __ldg(Wsub + r5 + t);
                float4 v6 = __ldg(Wsub + r6 + t);
                float4 v7 = __ldg(Wsub + r7 + t);
                acc.x += ((v0.x + v1.x) + (v2.x + v3.x)) + ((v4.x + v5.x) + (v6.x + v7.x));
                acc.y += ((v0.y + v1.y) + (v2.y + v3.y)) + ((v4.y + v5.y) + (v6.y + v7.y));
                acc.z += ((v0.z + v1.z) + (v2.z + v3.z)) + ((v4.z + v5.z) + (v6.z + v7.z));
                acc.w += ((v0.w + v1.w) + (v2.w + v3.w)) + ((v4.w + v5.w) + (v6.w + v7.w));
            }

            // tail: up to 7 loads, uniform predicates (j, n uniform per block)
            if (j < n) {
                float4 v0 = make_float4(0.f,0.f,0.f,0.f), v1 = v0, v2 = v0, v3 = v0;
                float4 v4 = v0, v5 = v0, v6 = v0;
                if (j + 0 < n) v0 = __ldg(Wsub + s_idx[j + 0] * D4 + t);
                if (j + 1 < n) v1 = __ldg(Wsub + s_idx[j + 1] * D4 + t);
                if (j + 2 < n) v2 = __ldg(Wsub + s_idx[j + 2] * D4 + t);
                if (j + 3 < n) v3 = __ldg(Wsub + s_idx[j + 3] * D4 + t);
                if (j + 4 < n) v4 = __ldg(Wsub + s_idx[j + 4] * D4 + t);
                if (j + 5 < n) v5 = __ldg(Wsub + s_idx[j + 5] * D4 + t);
                if (j + 6 < n) v6 = __ldg(Wsub + s_idx[j + 6] * D4 + t);
                acc.x += ((v0.x + v1.x) + (v2.x + v3.x)) + ((v4.x + v5.x) + v6.x);
                acc.y += ((v0.y + v1.y) + (v2.y + v3.y)) + ((v4.y + v5.y) + v6.y);
                acc.z += ((v0.z + v1.z) + (v2.z + v3.z)) + ((v4.z + v5.z) + v6.z);
                acc.w += ((v0.w + v1.w) + (v2.w + v3.w)) + ((v4.w + v5.w) + v6.w);
            }
        }
    }

    if (act) out[b * D4 + t] = acc;   // max offset 16384*75 fits int
}

extern "C" void kernel_launch(void* const* d_in, const int* in_sizes, int n_in,
                              void* d_out, int out_size)
{
    const int*    center = (const int*)d_in[0];
    const int*    ngram  = (const int*)d_in[1];
    const int*    seg    = (const int*)d_in[2];
    const float4* Win    = (const float4*)d_in[3];
    const float4* Wsub   = (const float4*)d_in[4];
    float4*       out    = (float4*)d_out;

    const int B     = in_sizes[0];
    const int total = in_sizes[1];

    ft_bag_kernel<<<B, 96>>>(center, ngram, seg, Win, Wsub, out, total);
}

// round 4
// speedup vs baseline: 1.2288x; 1.2288x over previous
#include <cuda_runtime.h>
#include <cstdint>

// FastText embedding-bag:
//   out[b,:] = W_in[center_ids[b],:] + sum_{i: seg[i]==b} W_sub[ngram_idx[i],:]
// seg sorted -> bag ranges precomputed by boundary kernel into g_off.
// D = 300 floats = 75 float4 per row (1200 B).
//
// R4: cp.async (LDGSTS) ring pipeline, depth 8 rows, per-thread 16B slices.
//     MLP lives in the L1/smem async queue instead of registers -> high
//     occupancy AND deep in-flight window. Binary search replaced by a
//     coalesced boundary-scatter prologue kernel.

#define D4    75
#define CHUNK 64
#define S     8          // ring depth (rows in flight per thread)
#define MAXB  65536

__device__ int g_off[MAXB + 1];

// ---------------------------------------------------------------- boundary
__global__ void bounds_kernel(const int* __restrict__ seg, int total, int B)
{
    int i = blockIdx.x * blockDim.x + threadIdx.x;
    if (i >= total) return;
    int cur  = seg[i];
    int prev = (i > 0) ? seg[i - 1] : -1;
    for (int b = prev + 1; b <= cur; ++b) g_off[b] = i;
    if (i == total - 1)
        for (int b = cur + 1; b <= B; ++b) g_off[b] = total;
}

// ---------------------------------------------------------------- helpers
__device__ __forceinline__ uint32_t smem_u32(const void* p)
{
    return (uint32_t)__cvta_generic_to_shared(p);
}
__device__ __forceinline__ void cp16(uint32_t s, const void* g)
{
    asm volatile("cp.async.cg.shared.global [%0], [%1], 16;\n" :: "r"(s), "l"(g));
}
__device__ __forceinline__ void cp_commit()
{
    asm volatile("cp.async.commit_group;\n" ::: "memory");
}
__device__ __forceinline__ void cp_wait_allbut7()
{
    asm volatile("cp.async.wait_group 7;\n" ::: "memory");
}

// ---------------------------------------------------------------- gather
__global__ void __launch_bounds__(96)
ft_bag_kernel(const int* __restrict__ center,
              const int* __restrict__ ngram,
              const float4* __restrict__ Win,
              const float4* __restrict__ Wsub,
              float4* __restrict__ out)
{
    const int b = blockIdx.x;
    const int t = threadIdx.x;
    const bool act = (t < D4);

    __shared__ int    s_idx[CHUNK];
    __shared__ float4 ring[S * D4];

    const int lo = g_off[b];
    const int hi = g_off[b + 1];

    // word vector (overlaps everything below)
    float4 acc = make_float4(0.f, 0.f, 0.f, 0.f);
    if (act) {
        const int crow = __ldg(center + b) * D4;
        acc = __ldg(Win + crow + t);
    }

    // this thread's byte address of slot 0 in the ring
    const uint32_t my0 = smem_u32(ring) + (uint32_t)t * 16u;

    for (int base = lo; base < hi; base += CHUNK) {
        const int n = min(hi - base, CHUNK);

        if (base != lo) __syncthreads();
        if (t < n) s_idx[t] = __ldg(ngram + base + t);
        __syncthreads();

        if (act) {
            // prologue: commit exactly S groups (empty if n < S)
            #pragma unroll
            for (int k = 0; k < S; ++k) {
                if (k < n) cp16(my0 + (uint32_t)k * (D4 * 16u),
                                Wsub + s_idx[k] * D4 + t);
                cp_commit();
            }
            // steady state: consume row j, refill row j+S
            #pragma unroll 1
            for (int j = 0; j < n; ++j) {
                cp_wait_allbut7();                 // committed=S+j, pending<=7 -> row j done
                const int slot = j & (S - 1);
                float4 v = ring[slot * D4 + t];    // own bytes only -> no barrier
                acc.x += v.x; acc.y += v.y;        // FADD forces LDS done before
                acc.z += v.z; acc.w += v.w;        // the cp16 below overwrites slot
                const int k = j + S;
                if (k < n) cp16(my0 + (uint32_t)slot * (D4 * 16u),
                                Wsub + s_idx[k] * D4 + t);
                cp_commit();                       // always: keeps group count aligned
            }
        }
    }

    if (act) out[b * D4 + t] = acc;
}

extern "C" void kernel_launch(void* const* d_in, const int* in_sizes, int n_in,
                              void* d_out, int out_size)
{
    const int*    center = (const int*)d_in[0];
    const int*    ngram  = (const int*)d_in[1];
    const int*    seg    = (const int*)d_in[2];
    const float4* Win    = (const float4*)d_in[3];
    const float4* Wsub   = (const float4*)d_in[4];
    float4*       out    = (float4*)d_out;

    const int B     = in_sizes[0];
    const int total = in_sizes[1];
    const int Bc    = (B > MAXB) ? MAXB : B;   // g_off capacity guard

    bounds_kernel<<<(total + 255) / 256, 256>>>(seg, total, Bc);
    ft_bag_kernel<<<B, 96>>>(center, ngram, Win, Wsub, out);
}